// round 13
// baseline (speedup 1.0000x reference)
#include <cuda_runtime.h>
#include <cstdint>

#define T_STEPS 512
#define B_SZ 128
#define I_SZ 256
#define H_SZ 256
#define BH (B_SZ*H_SZ)

typedef unsigned long long ull;

// ---------------- f32x2 helpers ----------------
__device__ __forceinline__ ull pack2(float x, float y) {
    ull r; asm("mov.b64 %0, {%1,%2};" : "=l"(r) : "f"(x), "f"(y)); return r;
}
__device__ __forceinline__ void unpack2(float& x, float& y, ull v) {
    asm("mov.b64 {%0,%1}, %2;" : "=f"(x), "=f"(y) : "l"(v));
}
__device__ __forceinline__ void fma2(ull& d, ull a, ull b) {
    asm("fma.rn.f32x2 %0, %1, %2, %0;" : "+l"(d) : "l"(a), "l"(b));
}

// ---------------- device scratch ----------------
__device__ float d_zx[4*B_SZ*I_SZ];                       // (4,B,I)
__device__ float d_zh[4*B_SZ*H_SZ];                       // (4,B,H)
__device__ float d_xpre[(size_t)T_STEPS*B_SZ*4*H_SZ];     // (T,B,4,H)
__device__ unsigned g_flags[128*32];                      // flag per (bi,ki), 128B apart

__global__ void reset_kernel() {
    int i = blockIdx.x * blockDim.x + threadIdx.x;
    if (i < 128*32) g_flags[i] = 0u;
}

// ---------------- masks ----------------
__device__ __forceinline__ float concrete_mask(float u) {
    const float EPSC = 1e-7f;
    float logit_p = logf(0.25f + EPSC) - logf(0.75f + EPSC);
    float lu = logf(u + EPSC) - logf(1.0f - u + EPSC);
    float x = (logit_p + lu) / 0.1f;
    float s = 1.0f / (1.0f + expf(-x));
    return (1.0f - s) / 0.75f;
}

__global__ void mask_kernel(const float* __restrict__ ux, const float* __restrict__ uh) {
    int i = blockIdx.x * blockDim.x + threadIdx.x;
    if (i < 4*B_SZ*I_SZ) {
        d_zx[i] = concrete_mask(ux[i]);
        d_zh[i] = concrete_mask(uh[i]);
    }
}

// ---------------- x_pre GEMM (BK=16, FFMA2) ----------------
#define XB_BM 128
#define XB_BN 64
#define XB_BK 16

__global__ __launch_bounds__(256) void xpre_kernel(
    const float* __restrict__ input, const float* __restrict__ W, const float* __restrict__ Wb)
{
    __shared__ float As[XB_BK][XB_BM+4];
    __shared__ float Bs[XB_BK][XB_BN+4];
    int g  = blockIdx.z;
    int t  = blockIdx.x;
    int n0 = blockIdx.y * XB_BN;
    int tid = threadIdx.x;
    int tx = tid & 15, ty = tid >> 4;

    ull acc[4][4];
    #pragma unroll
    for (int p = 0; p < 4; p++)
        #pragma unroll
        for (int c = 0; c < 4; c++) acc[p][c] = 0ull;

    const float* inpBase = input + (size_t)t * (B_SZ*I_SZ);
    const float* zxBase  = d_zx + g * (B_SZ*I_SZ);
    const float* wBase   = W + (size_t)g * (H_SZ*I_SZ) + (size_t)n0 * I_SZ;

    int lrow   = tid >> 2;
    int lchunk = (tid & 3) * 4;

    for (int kk0 = 0; kk0 < I_SZ; kk0 += XB_BK) {
        #pragma unroll
        for (int it = 0; it < 2; it++) {
            int row = lrow + it*64;
            float4 av = *(const float4*)(inpBase + row*I_SZ + kk0 + lchunk);
            float4 zv = *(const float4*)(zxBase  + row*I_SZ + kk0 + lchunk);
            As[lchunk+0][row] = av.x*zv.x;
            As[lchunk+1][row] = av.y*zv.y;
            As[lchunk+2][row] = av.z*zv.z;
            As[lchunk+3][row] = av.w*zv.w;
        }
        {
            float4 wv = *(const float4*)(wBase + lrow*I_SZ + kk0 + lchunk);
            Bs[lchunk+0][lrow] = wv.x;
            Bs[lchunk+1][lrow] = wv.y;
            Bs[lchunk+2][lrow] = wv.z;
            Bs[lchunk+3][lrow] = wv.w;
        }
        __syncthreads();
        #pragma unroll
        for (int kk = 0; kk < XB_BK; kk++) {
            float4 b4 = *(const float4*)&Bs[kk][tx*4];
            ulonglong2 a01 = *(const ulonglong2*)&As[kk][ty*8];
            ulonglong2 a23 = *(const ulonglong2*)&As[kk][ty*8+4];
            ull ap[4] = {a01.x, a01.y, a23.x, a23.y};
            ull bb[4] = {pack2(b4.x,b4.x), pack2(b4.y,b4.y),
                         pack2(b4.z,b4.z), pack2(b4.w,b4.w)};
            #pragma unroll
            for (int p = 0; p < 4; p++)
                #pragma unroll
                for (int c = 0; c < 4; c++)
                    fma2(acc[p][c], ap[p], bb[c]);
        }
        __syncthreads();
    }
    float4 wb = *(const float4*)(Wb + g*H_SZ + n0 + tx*4);
    #pragma unroll
    for (int p = 0; p < 4; p++) {
        float lo[4], hi[4];
        #pragma unroll
        for (int c = 0; c < 4; c++) unpack2(lo[c], hi[c], acc[p][c]);
        int b0r = ty*8 + 2*p;
        size_t o0 = (((size_t)t*B_SZ + b0r)*4 + g) * H_SZ + n0 + tx*4;
        size_t o1 = (((size_t)t*B_SZ + b0r+1)*4 + g) * H_SZ + n0 + tx*4;
        *(float4*)(d_xpre + o0) = make_float4(lo[0]+wb.x, lo[1]+wb.y, lo[2]+wb.z, lo[3]+wb.w);
        *(float4*)(d_xpre + o1) = make_float4(hi[0]+wb.x, hi[1]+wb.y, hi[2]+wb.z, hi[3]+wb.w);
    }
}

// ---------------- persistent recurrent kernel: dataflow-pipelined ----------------
// 128 CTAs (8 b-groups x 16 k-CTAs), 256 threads. NO global barrier:
// producer flags (one writer each) + per-warp chunk consumption.
// smem: U_s[16][UQB] | hm_s[16][HQB] (duplicated pairs) | s_s | c_s
#define RK_THREADS 256
#define UQB 1032                     // 64*16 + 8
#define HQB 2056                     // 64*32 + 8 (duplicated-pair rows)
#define SST 20                       // 80B row stride (float4-aligned)
#define RK_SMEM_FLOATS (16*UQB + 16*HQB + 4*4*16*SST + 256)
#define RK_SMEM_BYTES (RK_SMEM_FLOATS*4)

__global__ __launch_bounds__(RK_THREADS, 1) void recurrent_kernel(
    const float* __restrict__ U, const float* __restrict__ Ub, float* __restrict__ out)
{
    extern __shared__ float sm[];
    float* U_s  = sm;                        // 16512
    float* hm_s = U_s + 16*UQB;              // 32896
    float* s_s  = hm_s + 16*HQB;             // 5120
    float* c_s  = s_s + 4*4*16*SST;          // 256

    int tid = threadIdx.x;
    int bi = blockIdx.x >> 4;  int b0 = bi * 16;
    int ki = blockIdx.x & 15;  int k0 = ki * 16;

    // ---- one-time loads ----
    for (int e = tid; e < 16384; e += RK_THREADS) {       // U_s[(g,hq)][h_in*16+k]
        int g = e >> 12; int k = (e >> 8) & 15; int h = e & 255;
        U_s[(g*4 + (h >> 6))*UQB + (h & 63)*16 + k] =
            U[((size_t)(g*H_SZ + k0 + k))*H_SZ + h];
    }
    for (int e = tid; e < 16*HQB; e += RK_THREADS) hm_s[e] = 0.f;   // t=0 state
    c_s[tid] = 0.f;

    // ---- consumer-chunk assignment (fixed per thread) ----
    // warp w handles chunks 2w, 2w+1; lane: 16 lanes per chunk.
    // lane-in-chunk ll: b2 = ll&7 -> local batches {2b2, 2b2+1}; kh = ll>>3 -> h-sub 8.
    int w = tid >> 5, lane = tid & 31;
    int jchunk = 2*w + (lane >> 4);
    int ll = lane & 15;
    int cb2 = ll & 7;                 // local b pair base
    int ckh = ll >> 3;                // 0/1: which 8-h half of the chunk
    int hq_j = jchunk >> 2;                        // quarter of this chunk
    int h_in_base = (jchunk & 3)*16 + ckh*8;       // h_in within quarter

    // zh registers for staging: zA/zB[g][kk] for (b=2b2 / 2b2+1, h = jchunk*16+ckh*8+kk)
    float zA[4][8], zB[4][8];
    {
        int hg = jchunk*16 + ckh*8;
        #pragma unroll
        for (int g = 0; g < 4; g++)
            #pragma unroll
            for (int kk = 0; kk < 8; kk++) {
                zA[g][kk] = d_zh[((size_t)(g*B_SZ + b0 + 2*cb2))*H_SZ + hg + kk];
                zB[g][kk] = d_zh[((size_t)(g*B_SZ + b0 + 2*cb2+1))*H_SZ + hg + kk];
            }
    }
    float* hmdst[4];
    #pragma unroll
    for (int g = 0; g < 4; g++)
        hmdst[g] = hm_s + (g*4 + hq_j)*HQB + h_in_base*32 + 4*cb2;

    unsigned* myflagpoll = &g_flags[(bi*16 + jchunk)*32];
    unsigned* myflagset  = &g_flags[(bi*16 + ki)*32];

    // ---- GEMM layout (as r11): 8 warps = (hH,g); lane = (hq2, bq, kq) ----
    int g   = w & 3;
    int hH  = w >> 2;
    int kq  = lane & 3;
    int bq  = (lane >> 2) & 3;
    int hq  = hH*2 + (lane >> 4);
    const float* Ug = U_s  + (g*4 + hq)*UQB + kq*4;
    const float* Hm = hm_s + (g*4 + hq)*HQB + 8*bq;
    float* Sbase = s_s + ((hq*4 + g)*16 + kq*4)*SST + 4*bq;

    // ---- epilogue mapping ----
    int eb = tid >> 4, ek = tid & 15;
    float ubr[4];
    #pragma unroll
    for (int gg = 0; gg < 4; gg++) ubr[gg] = Ub[gg*H_SZ + k0 + ek];
    __syncthreads();

    float* hn     = out;
    float* ht_out = out + (size_t)T_STEPS*BH;
    float* ct_out = ht_out + BH;

    // initial x_pre prefetch (t=0)
    const float* xpp = d_xpre + (((size_t)(b0 + eb))*4)*H_SZ + k0 + ek;
    float xp0 = __ldcs(xpp);
    float xp1 = __ldcs(xpp + H_SZ);
    float xp2 = __ldcs(xpp + 2*H_SZ);
    float xp3 = __ldcs(xpp + 3*H_SZ);

    for (int t = 0; t < T_STEPS; t++) {
        // ---- phase 1: consume h chunks as they arrive, stage hm (dup pairs) ----
        if (t > 0) {
            unsigned v;
            do {
                asm volatile("ld.acquire.gpu.u32 %0, [%1];" : "=r"(v) : "l"(myflagpoll));
            } while (v < (unsigned)t);
            const float* src = hn + (size_t)(t-1)*BH + (size_t)(b0 + 2*cb2)*H_SZ
                             + jchunk*16 + ckh*8;
            float4 r00 = __ldcg((const float4*)(src));
            float4 r01 = __ldcg((const float4*)(src + 4));
            float4 r10 = __ldcg((const float4*)(src + H_SZ));
            float4 r11 = __ldcg((const float4*)(src + H_SZ + 4));
            float v0[8] = {r00.x,r00.y,r00.z,r00.w, r01.x,r01.y,r01.z,r01.w};
            float v1[8] = {r10.x,r10.y,r10.z,r10.w, r11.x,r11.y,r11.z,r11.w};
            #pragma unroll
            for (int kk = 0; kk < 8; kk++) {
                #pragma unroll
                for (int gg = 0; gg < 4; gg++) {
                    float p0 = v0[kk]*zA[gg][kk];
                    float p1 = v1[kk]*zB[gg][kk];
                    *(float4*)(hmdst[gg] + kk*32) = make_float4(p0, p0, p1, p1);
                }
            }
        }
        __syncthreads();

        // ---- phase 2: recurrent GEMM, 4k x 4b per thread over 64 h ----
        {
            ull a0[2] = {0ull,0ull}, a1[2] = {0ull,0ull};
            ull a2[2] = {0ull,0ull}, a3[2] = {0ull,0ull};
            #pragma unroll 8
            for (int h = 0; h < 64; h++) {
                ulonglong2 u2 = *(const ulonglong2*)(Ug + h*16);
                ulonglong2 mA = *(const ulonglong2*)(Hm + h*32);
                ulonglong2 mB = *(const ulonglong2*)(Hm + h*32 + 4);
                fma2(a0[0], u2.x, mA.x); fma2(a0[1], u2.y, mA.x);
                fma2(a1[0], u2.x, mA.y); fma2(a1[1], u2.y, mA.y);
                fma2(a2[0], u2.x, mB.x); fma2(a2[1], u2.y, mB.x);
                fma2(a3[0], u2.x, mB.y); fma2(a3[1], u2.y, mB.y);
            }
            float f0[4], f1[4], f2[4], f3[4];
            unpack2(f0[0], f0[1], a0[0]); unpack2(f0[2], f0[3], a0[1]);
            unpack2(f1[0], f1[1], a1[0]); unpack2(f1[2], f1[3], a1[1]);
            unpack2(f2[0], f2[1], a2[0]); unpack2(f2[2], f2[3], a2[1]);
            unpack2(f3[0], f3[1], a3[0]); unpack2(f3[2], f3[3], a3[1]);
            #pragma unroll
            for (int kk = 0; kk < 4; kk++)
                *(float4*)(Sbase + kk*SST) = make_float4(f0[kk], f1[kk], f2[kk], f3[kk]);
        }
        __syncthreads();

        // ---- phase 3: epilogue ----
        {
            float s[4];
            #pragma unroll
            for (int gg = 0; gg < 4; gg++) {
                float vv = ubr[gg];
                #pragma unroll
                for (int qq = 0; qq < 4; qq++)
                    vv += s_s[((qq*4 + gg)*16 + ek)*SST + eb];
                s[gg] = vv;
            }
            s[0] += xp0; s[1] += xp1; s[2] += xp2; s[3] += xp3;
            float iv = __fdividef(1.f, 1.f + __expf(-s[0]));
            float fv = __fdividef(1.f, 1.f + __expf(-s[1]));
            float ov = __fdividef(1.f, 1.f + __expf(-s[2]));
            float gv = __fdividef(2.f, 1.f + __expf(-2.f*s[3])) - 1.f;
            float c  = fv * c_s[tid] + iv * gv;
            c_s[tid] = c;
            float th = __fdividef(2.f, 1.f + __expf(-2.f*c)) - 1.f;
            float hval = ov * th;
            __stcg(&hn[(size_t)t*BH + (b0+eb)*H_SZ + k0+ek], hval);
            if (t == T_STEPS-1) {
                ht_out[(b0+eb)*H_SZ + k0+ek] = hval;
                ct_out[(b0+eb)*H_SZ + k0+ek] = c;
            }
        }

        // ---- phase 4: publish our h chunk (single-writer flag, release) ----
        if (t < T_STEPS-1) {
            const float* xpn = d_xpre + (((size_t)(t+1)*B_SZ + b0 + eb)*4)*H_SZ + k0 + ek;
            xp0 = __ldcs(xpn);
            xp1 = __ldcs(xpn + H_SZ);
            xp2 = __ldcs(xpn + 2*H_SZ);
            xp3 = __ldcs(xpn + 3*H_SZ);
            __syncthreads();          // all CTA h-stores precede the release
            if (tid == 0) {
                unsigned nv = (unsigned)(t+1);
                asm volatile("st.release.gpu.u32 [%0], %1;" :: "l"(myflagset), "r"(nv) : "memory");
            }
        }
    }
}

// ---------------- launcher ----------------
extern "C" void kernel_launch(void* const* d_in, const int* in_sizes, int n_in,
                              void* d_out, int out_size) {
    const float* input = (const float*)d_in[0];
    const float* ux    = (const float*)d_in[1];
    const float* uh    = (const float*)d_in[2];
    const float* W     = (const float*)d_in[3];
    const float* Wb    = (const float*)d_in[4];
    const float* U     = (const float*)d_in[5];
    const float* Ub    = (const float*)d_in[6];
    float* out = (float*)d_out;

    (void)in_sizes; (void)n_in; (void)out_size;

    cudaFuncSetAttribute(recurrent_kernel,
                         cudaFuncAttributeMaxDynamicSharedMemorySize, RK_SMEM_BYTES);

    reset_kernel<<<16, 256>>>();
    mask_kernel<<<512, 256>>>(ux, uh);
    xpre_kernel<<<dim3(T_STEPS, 4, 4), 256>>>(input, W, Wb);
    recurrent_kernel<<<128, RK_THREADS, RK_SMEM_BYTES>>>(U, Ub, out);
}